// round 14
// baseline (speedup 1.0000x reference)
#include <cuda_runtime.h>
#include <math.h>

// Fixed shapes: kernels [1,8192,256] f32, categories [1,8192] i32, scores [1,8192] f32
#define NN   8192
#define DD   256
#define D4   64
#define NC   128
#define TS   32
#define H4   16          // head = first 64 dims (DO NOT shrink: C-S bound needs 64 dims)
#define PH   17          // head pitch in float4 (16+1 -> conflict-free)
#define THRESH 0.95f
#define EPSN 1e-8f
#define OCC  4
#define GRID (148 * OCC) // 592 = 8 * 74; all blocks co-resident (required for gbar)
#define NT   256

// Output: ALL float32, concatenated:
//   fused [NN*DD] @0, cats [NN] @NN*DD, scores [NN] @NN*DD+NN, keep [NN] @NN*DD+2*NN

// ---------------- device scratch ----------------
// Invariant: g_cnt[], g_dirty, g_sub[], g_master, g_done ZERO at entry
// (static init; re-zeroed by the last-exiting block every run).
__device__ float g_invn[NN];
__device__ float g_tail[NN];          // ||normalized tail (dims 64..255)||
__device__ int   g_cnt[NC];           // scatter fill counter (== final counts)
__device__ int   g_buck[NC * NN];     // fixed-base member buckets
__device__ int   g_claim[NN];
__device__ int   g_cnt2[NN];
__device__ int   g_dirty;
__device__ unsigned g_sub[8];         // split barrier arrival counters
__device__ unsigned g_master;
__device__ unsigned g_done;           // post-P3 exit counter
__device__ unsigned g_bar_gen = 0;    // monotonically increasing across replays (harmless)

static __device__ __forceinline__ int clamp_cat(int ci) {
    if (ci < 0) ci = 0;
    if (ci > NC - 1) ci = NC - 1;
    return ci;
}

static __device__ __forceinline__ unsigned ld_acq(const unsigned* p) {
    unsigned v;
    asm volatile("ld.acquire.gpu.u32 %0, [%1];" : "=r"(v) : "l"(p) : "memory");
    return v;
}

// Grid-wide barrier with split arrival counters (8 x 74 = 592).
// Safe because all GRID blocks are co-resident.
static __device__ __forceinline__ void gbar_split() {
    __threadfence();
    __syncthreads();
    if (threadIdx.x == 0) {
        unsigned gen = ld_acq(&g_bar_gen);
        unsigned pos = atomicAdd(&g_sub[blockIdx.x & 7], 1u);
        if (pos == (GRID / 8) - 1) {                  // last in sub-group
            if (atomicAdd(&g_master, 1u) == 7u)       // last sub-group
                atomicAdd(&g_bar_gen, 1u);
        }
        while (ld_acq(&g_bar_gen) == gen) { __nanosleep(32); }
        __threadfence();
    }
    __syncthreads();
}

__global__ void __launch_bounds__(NT, OCC) k_all(const float* __restrict__ kin,
                                                 const int* __restrict__ cat,
                                                 const float* __restrict__ scores,
                                                 float* __restrict__ out) {
    extern __shared__ float4 sm[];      // sA[TS*PH] + sB[TS*PH]
    const int t = threadIdx.x;
    const int lane = t & 31, wp = t >> 5;
    const float4* k4g = (const float4*)kin;
    float4* out4 = (float4*)out;

    // ---------- P0: norms + tails + bucket scatter + DEFAULT OUTPUTS ----------
    {
        int r0 = blockIdx.x * 16 + wp * 2;      // 592*16 = 9472 >= 8192
        if (r0 < NN) {
            int r1 = r0 + 1;
            float4 a0 = k4g[r0 * D4 + lane];
            float4 b0 = k4g[r0 * D4 + 32 + lane];
            float4 a1 = k4g[r1 * D4 + lane];
            float4 b1 = k4g[r1 * D4 + 32 + lane];
            // default fused = kernels (fixed up later only if dirty)
            out4[r0 * D4 + lane]      = a0;
            out4[r0 * D4 + 32 + lane] = b0;
            out4[r1 * D4 + lane]      = a1;
            out4[r1 * D4 + 32 + lane] = b1;
            float asq0 = a0.x*a0.x + a0.y*a0.y + a0.z*a0.z + a0.w*a0.w;
            float bsq0 = b0.x*b0.x + b0.y*b0.y + b0.z*b0.z + b0.w*b0.w;
            float asq1 = a1.x*a1.x + a1.y*a1.y + a1.z*a1.z + a1.w*a1.w;
            float bsq1 = b1.x*b1.x + b1.y*b1.y + b1.z*b1.z + b1.w*b1.w;
            float s0 = asq0 + bsq0, s1 = asq1 + bsq1;
            float h0 = (lane < H4) ? asq0 : 0.0f;   // head = dims 0..63
            float h1 = (lane < H4) ? asq1 : 0.0f;
            #pragma unroll
            for (int o = 16; o; o >>= 1) {
                s0 += __shfl_xor_sync(0xFFFFFFFFu, s0, o);
                s1 += __shfl_xor_sync(0xFFFFFFFFu, s1, o);
                h0 += __shfl_xor_sync(0xFFFFFFFFu, h0, o);
                h1 += __shfl_xor_sync(0xFFFFFFFFu, h1, o);
            }
            if (lane < 2) {
                int row = (lane == 0) ? r0 : r1;
                float s = (lane == 0) ? s0 : s1;
                float h = (lane == 0) ? h0 : h1;
                float invn = 1.0f / fmaxf(sqrtf(s), EPSN);
                g_invn[row]  = invn;
                float headfrac = h * invn * invn;
                g_tail[row]  = sqrtf(fmaxf(0.0f, 1.0f - headfrac));
                g_claim[row] = row;
                g_cnt2[row]  = 0;
                // default tail outputs (keep=true); fixed up only if dirty
                out[NN * DD + row]          = (float)cat[row];
                out[NN * DD + NN + row]     = scores[row];
                out[NN * DD + 2 * NN + row] = 1.0f;
                int ci = clamp_cat(cat[row]);
                int pos = atomicAdd(&g_cnt[ci], 1);
                g_buck[ci * NN + pos] = row;
            }
        }
    }
    gbar_split();    // the ONLY full grid barrier

    // ---------- P3: pair tiles, static assignment + binary-search decode ----------
    {
        __shared__ int s_cnt[NC], s_tp[NC + 1];
        __shared__ int wsp[8];
        {
            int c = 0, tp = 0;
            if (t < NC) {
                c = __ldcg(&g_cnt[t]);
                int T = (c + TS - 1) / TS;
                tp = T * (T + 1) / 2;
                s_cnt[t] = c;
            }
            int ip = tp;
            #pragma unroll
            for (int o = 1; o < 32; o <<= 1) {
                int v = __shfl_up_sync(0xFFFFFFFFu, ip, o);
                if (lane >= o) ip += v;
            }
            if (lane == 31 && wp < 4) wsp[wp] = ip;
            __syncthreads();
            if (t < NC) {
                int op = 0;
                #pragma unroll
                for (int ww = 0; ww < 4; ww++)
                    if (ww < wp) op += wsp[ww];
                s_tp[t] = ip + op - tp;   // exclusive prefix
                if (t == NC - 1) s_tp[NC] = ip + op;
            }
            __syncthreads();
        }
        const int total = s_tp[NC];

        float4* sA = sm;
        float4* sB = sm + TS * PH;
        __shared__ int gA[TS], gB[TS];
        __shared__ float sTailA[TS], sTailB[TS];

        for (int w = blockIdx.x; w < total; w += GRID) {
            int lo = 0, hi = NC;
            #pragma unroll
            for (int it = 0; it < 7; it++) {
                int mid = (lo + hi) >> 1;
                if (w >= s_tp[mid]) lo = mid; else hi = mid;
            }
            int c = lo;
            int p = w - s_tp[c];
            int cc = s_cnt[c];
            int T = (cc + TS - 1) / TS;
            int ta = 0;
            while (p >= T - ta) { p -= T - ta; ta++; }
            int tb = ta + p;
            int rowA = c * NN + ta * TS;
            int rowB = c * NN + tb * TS;
            int na = min(TS, cc - ta * TS);
            int nb = min(TS, cc - tb * TS);

            if (t < TS) {
                int a = (t < na) ? __ldcg(&g_buck[rowA + t]) : -1;
                int b = (t < nb) ? __ldcg(&g_buck[rowB + t]) : -1;
                gA[t] = a; gB[t] = b;
                sTailA[t] = (a >= 0) ? g_tail[a] : 0.0f;
                sTailB[t] = (b >= 0) ? g_tail[b] : 0.0f;
            }
            __syncthreads();

            for (int i = t; i < TS * H4; i += NT) {
                int r = i >> 4, k4 = i & 15;
                float4 va = make_float4(0.f, 0.f, 0.f, 0.f);
                int g = gA[r];
                if (g >= 0) {
                    va = k4g[g * D4 + k4];
                    float sc = g_invn[g];
                    va.x *= sc; va.y *= sc; va.z *= sc; va.w *= sc;
                }
                sA[r * PH + k4] = va;
                float4 vb = make_float4(0.f, 0.f, 0.f, 0.f);
                g = gB[r];
                if (g >= 0) {
                    vb = k4g[g * D4 + k4];
                    float sc = g_invn[g];
                    vb.x *= sc; vb.y *= sc; vb.z *= sc; vb.w *= sc;
                }
                sB[r * PH + k4] = vb;
            }
            __syncthreads();

            int ra = t & 31;
            int rq = t >> 5;
            float a0 = 0.f, a1 = 0.f, a2 = 0.f, a3 = 0.f;
            #pragma unroll
            for (int k4 = 0; k4 < H4; k4++) {
                float4 a  = sA[ra * PH + k4];
                float4 b0 = sB[(rq      ) * PH + k4];
                float4 b1 = sB[(rq +  8 ) * PH + k4];
                float4 b2 = sB[(rq + 16 ) * PH + k4];
                float4 b3 = sB[(rq + 24 ) * PH + k4];
                a0 += a.x * b0.x + a.y * b0.y + a.z * b0.z + a.w * b0.w;
                a1 += a.x * b1.x + a.y * b1.y + a.z * b1.z + a.w * b1.w;
                a2 += a.x * b2.x + a.y * b2.y + a.z * b2.z + a.w * b2.w;
                a3 += a.x * b3.x + a.y * b3.y + a.z * b3.z + a.w * b3.w;
            }
            if (ra < na) {
                int ga = gA[ra];
                float tA = sTailA[ra];
                float accs[4] = {a0, a1, a2, a3};
                #pragma unroll
                for (int j = 0; j < 4; j++) {
                    int rb = rq + 8 * j;
                    if (rb < nb) {
                        int gb = gB[rb];
                        if (gb != ga && accs[j] + tA * sTailB[rb] >= THRESH) {
                            // C-S bound passed: exact full 256-dim dot from L2
                            float invA = g_invn[ga], invB = g_invn[gb];
                            float d = 0.0f;
                            for (int k = 0; k < D4; k++) {
                                float4 x = __ldg(&k4g[ga * D4 + k]);
                                float4 y = __ldg(&k4g[gb * D4 + k]);
                                d += x.x * y.x + x.y * y.y + x.z * y.z + x.w * y.w;
                            }
                            if (d * invA * invB >= THRESH) {
                                int lo2 = min(ga, gb), hi2 = max(ga, gb);
                                atomicMin(&g_claim[hi2], lo2);
                                g_dirty = 1;
                            }
                        }
                    }
                }
            }
            __syncthreads();
        }
    }

    // ---------- exit protocol: all but the LAST block leave immediately ----------
    // threadfence makes this block's out-defaults + claim atomics globally visible
    // BEFORE its done-arrival; the last block therefore sees everything.
    __threadfence();
    __syncthreads();
    __shared__ int s_last;
    if (t == 0) s_last = (atomicAdd(&g_done, 1u) == GRID - 1) ? 1 : 0;
    __syncthreads();
    if (!s_last) return;

    // ======== LAST BLOCK ONLY from here ========
    const int dirty = __ldcg(&g_dirty);

    if (dirty) {
        // SLOW PATH (rare): exact fixup, single block.
        // Phase A: counts + tail fixes + zeroing
        for (int idx = t; idx < NN; idx += NT) {
            int c = __ldcg(&g_claim[idx]);
            bool keep = (c == idx);
            bool owner_kept = (__ldcg(&g_claim[c]) == c);
            if (owner_kept) atomicAdd(&g_cnt2[c], 1);
            if (!keep) {
                out[NN * DD + idx]          = -1.0f;
                out[NN * DD + NN + idx]     = 0.0f;
                out[NN * DD + 2 * NN + idx] = 0.0f;
                float4 z = make_float4(0.f, 0.f, 0.f, 0.f);
                #pragma unroll 4
                for (int k = 0; k < D4; k++) out4[idx * D4 + k] = z;
                if (owner_kept) {
                    #pragma unroll 4
                    for (int k = 0; k < D4; k++) out4[c * D4 + k] = z;
                }
            }
        }
        __syncthreads();
        // Phase B: accumulate multi-member clusters (warp per row)
        for (int j = wp; j < NN; j += 8) {
            int i = 0, n = 0;
            if (lane == 0) {
                i = __ldcg(&g_claim[j]);
                n = (__ldcg(&g_claim[i]) == i) ? __ldcg(&g_cnt2[i]) : 0;
            }
            i = __shfl_sync(0xFFFFFFFFu, i, 0);
            n = __shfl_sync(0xFFFFFFFFu, n, 0);
            if (n <= 1) continue;   // n==1 singleton already correct; n==0 owner dropped
            float4 v0 = k4g[j * D4 + lane];
            float4 v1 = k4g[j * D4 + 32 + lane];
            float w = 1.0f / (float)n;
            atomicAdd(&out[j >= 0 ? i * DD + lane * 4 + 0 : 0], v0.x * w);
            atomicAdd(&out[i * DD + lane * 4 + 1],       v0.y * w);
            atomicAdd(&out[i * DD + lane * 4 + 2],       v0.z * w);
            atomicAdd(&out[i * DD + lane * 4 + 3],       v0.w * w);
            atomicAdd(&out[i * DD + 128 + lane * 4 + 0], v1.x * w);
            atomicAdd(&out[i * DD + 128 + lane * 4 + 1], v1.y * w);
            atomicAdd(&out[i * DD + 128 + lane * 4 + 2], v1.z * w);
            atomicAdd(&out[i * DD + 128 + lane * 4 + 3], v1.w * w);
        }
        __syncthreads();
    }

    // restore ALL invariants for the next graph replay (g_bar_gen stays monotonic)
    if (t < NC) g_cnt[t] = 0;
    if (t < 8)  g_sub[t] = 0;
    if (t == 8)  g_master = 0;
    if (t == 9)  g_done = 0;
    if (t == 10) g_dirty = 0;
}

// ---------------- launch ----------------
extern "C" void kernel_launch(void* const* d_in, const int* in_sizes, int n_in,
                              void* d_out, int out_size) {
    const float* kin    = (const float*)d_in[0];
    const int*   cat    = (const int*)d_in[1];
    const float* scores = (const float*)d_in[2];
    float*       out    = (float*)d_out;

    (void)in_sizes; (void)n_in; (void)out_size;

    const int smem = 2 * TS * PH * (int)sizeof(float4);  // 17,408 B
    cudaFuncSetAttribute(k_all, cudaFuncAttributeMaxDynamicSharedMemorySize, smem);

    k_all<<<GRID, NT, smem>>>(kin, cat, scores, out);
}

// round 15
// speedup vs baseline: 1.0097x; 1.0097x over previous
#include <cuda_runtime.h>
#include <math.h>

// Fixed shapes: kernels [1,8192,256] f32, categories [1,8192] i32, scores [1,8192] f32
#define NN   8192
#define DD   256
#define D4   64
#define NC   128
#define TS   32
#define H4   16          // head = first 64 dims (DO NOT shrink: C-S bound needs 64 dims)
#define PH   17          // head pitch in float4 (16+1 -> conflict-free)
#define THRESH 0.95f
#define EPSN 1e-8f
#define OCC  4
#define GRID (148 * OCC) // 592 = 8 * 74; all blocks co-resident (required for gbar)
#define NT   256

// Output: ALL float32, concatenated:
//   fused [NN*DD] @0, cats [NN] @NN*DD, scores [NN] @NN*DD+NN, keep [NN] @NN*DD+2*NN

// ---------------- device scratch ----------------
// Invariant: g_cnt[], g_dirty, g_sub[], g_master, g_done ZERO at entry
// (static init; re-zeroed by the last-exiting block every run).
__device__ float g_invn[NN];
__device__ int   g_cnt[NC];           // scatter fill counter (== final counts)
__device__ int2  g_buck[NC * NN];     // packed {row, tail_bits} member buckets
__device__ int   g_claim[NN];
__device__ int   g_cnt2[NN];
__device__ int   g_dirty;
__device__ unsigned g_sub[8];         // split barrier arrival counters
__device__ unsigned g_master;
__device__ unsigned g_done;           // post-P3 exit counter
__device__ unsigned g_bar_gen = 0;    // monotonically increasing across replays (harmless)

static __device__ __forceinline__ int clamp_cat(int ci) {
    if (ci < 0) ci = 0;
    if (ci > NC - 1) ci = NC - 1;
    return ci;
}

static __device__ __forceinline__ unsigned ld_acq(const unsigned* p) {
    unsigned v;
    asm volatile("ld.acquire.gpu.u32 %0, [%1];" : "=r"(v) : "l"(p) : "memory");
    return v;
}

// Grid-wide barrier with split arrival counters (8 x 74 = 592).
// Safe because all GRID blocks are co-resident.
static __device__ __forceinline__ void gbar_split() {
    __threadfence();
    __syncthreads();
    if (threadIdx.x == 0) {
        unsigned gen = ld_acq(&g_bar_gen);
        unsigned pos = atomicAdd(&g_sub[blockIdx.x & 7], 1u);
        if (pos == (GRID / 8) - 1) {                  // last in sub-group
            if (atomicAdd(&g_master, 1u) == 7u)       // last sub-group
                atomicAdd(&g_bar_gen, 1u);
        }
        while (ld_acq(&g_bar_gen) == gen) { __nanosleep(32); }
        __threadfence();
    }
    __syncthreads();
}

__global__ void __launch_bounds__(NT, OCC) k_all(const float* __restrict__ kin,
                                                 const int* __restrict__ cat,
                                                 const float* __restrict__ scores,
                                                 float* __restrict__ out) {
    extern __shared__ float4 sm[];      // sA[TS*PH] + sB[TS*PH]
    const int t = threadIdx.x;
    const int lane = t & 31, wp = t >> 5;
    const float4* k4g = (const float4*)kin;
    float4* out4 = (float4*)out;

    // ---------- P0: norms + tails + packed bucket scatter + DEFAULT OUTPUTS ----------
    {
        int r0 = blockIdx.x * 16 + wp * 2;      // 592*16 = 9472 >= 8192
        if (r0 < NN) {
            int r1 = r0 + 1;
            float4 a0 = k4g[r0 * D4 + lane];
            float4 b0 = k4g[r0 * D4 + 32 + lane];
            float4 a1 = k4g[r1 * D4 + lane];
            float4 b1 = k4g[r1 * D4 + 32 + lane];
            // default fused = kernels (fixed up later only if dirty)
            out4[r0 * D4 + lane]      = a0;
            out4[r0 * D4 + 32 + lane] = b0;
            out4[r1 * D4 + lane]      = a1;
            out4[r1 * D4 + 32 + lane] = b1;
            float asq0 = a0.x*a0.x + a0.y*a0.y + a0.z*a0.z + a0.w*a0.w;
            float bsq0 = b0.x*b0.x + b0.y*b0.y + b0.z*b0.z + b0.w*b0.w;
            float asq1 = a1.x*a1.x + a1.y*a1.y + a1.z*a1.z + a1.w*a1.w;
            float bsq1 = b1.x*b1.x + b1.y*b1.y + b1.z*b1.z + b1.w*b1.w;
            float s0 = asq0 + bsq0, s1 = asq1 + bsq1;
            float h0 = (lane < H4) ? asq0 : 0.0f;   // head = dims 0..63
            float h1 = (lane < H4) ? asq1 : 0.0f;
            #pragma unroll
            for (int o = 16; o; o >>= 1) {
                s0 += __shfl_xor_sync(0xFFFFFFFFu, s0, o);
                s1 += __shfl_xor_sync(0xFFFFFFFFu, s1, o);
                h0 += __shfl_xor_sync(0xFFFFFFFFu, h0, o);
                h1 += __shfl_xor_sync(0xFFFFFFFFu, h1, o);
            }
            if (lane < 2) {
                int row = (lane == 0) ? r0 : r1;
                float s = (lane == 0) ? s0 : s1;
                float h = (lane == 0) ? h0 : h1;
                float invn = 1.0f / fmaxf(sqrtf(s), EPSN);
                g_invn[row]  = invn;
                float headfrac = h * invn * invn;
                float tailv = sqrtf(fmaxf(0.0f, 1.0f - headfrac));
                g_claim[row] = row;
                g_cnt2[row]  = 0;
                // default tail outputs (keep=true); fixed up only if dirty
                out[NN * DD + row]          = (float)cat[row];
                out[NN * DD + NN + row]     = scores[row];
                out[NN * DD + 2 * NN + row] = 1.0f;
                int ci = clamp_cat(cat[row]);
                int pos = atomicAdd(&g_cnt[ci], 1);
                g_buck[ci * NN + pos] = make_int2(row, __float_as_int(tailv));
            }
        }
    }
    gbar_split();    // the ONLY full grid barrier

    // ---------- P3: pair tiles, static assignment + binary-search decode ----------
    {
        __shared__ int s_cnt[NC], s_tp[NC + 1];
        __shared__ int wsp[8];
        {
            int c = 0, tp = 0;
            if (t < NC) {
                c = __ldcg(&g_cnt[t]);
                int T = (c + TS - 1) / TS;
                tp = T * (T + 1) / 2;
                s_cnt[t] = c;
            }
            int ip = tp;
            #pragma unroll
            for (int o = 1; o < 32; o <<= 1) {
                int v = __shfl_up_sync(0xFFFFFFFFu, ip, o);
                if (lane >= o) ip += v;
            }
            if (lane == 31 && wp < 4) wsp[wp] = ip;
            __syncthreads();
            if (t < NC) {
                int op = 0;
                #pragma unroll
                for (int ww = 0; ww < 4; ww++)
                    if (ww < wp) op += wsp[ww];
                s_tp[t] = ip + op - tp;   // exclusive prefix
                if (t == NC - 1) s_tp[NC] = ip + op;
            }
            __syncthreads();
        }
        const int total = s_tp[NC];

        float4* sA = sm;
        float4* sB = sm + TS * PH;
        __shared__ int gA[TS], gB[TS];
        __shared__ float sTailA[TS], sTailB[TS];

        for (int w = blockIdx.x; w < total; w += GRID) {
            int lo = 0, hi = NC;
            #pragma unroll
            for (int it = 0; it < 7; it++) {
                int mid = (lo + hi) >> 1;
                if (w >= s_tp[mid]) lo = mid; else hi = mid;
            }
            int c = lo;
            int p = w - s_tp[c];
            int cc = s_cnt[c];
            int T = (cc + TS - 1) / TS;
            int ta = 0;
            while (p >= T - ta) { p -= T - ta; ta++; }
            int tb = ta + p;
            const bool diag = (tb == ta);
            int rowA = c * NN + ta * TS;
            int rowB = c * NN + tb * TS;
            int na = min(TS, cc - ta * TS);
            int nb = min(TS, cc - tb * TS);

            if (t < TS) {
                int a = -1; float tla = 0.0f;
                if (t < na) {
                    int2 e = __ldcg(&g_buck[rowA + t]);      // single 8B load, no chain
                    a = e.x; tla = __int_as_float(e.y);
                }
                gA[t] = a; sTailA[t] = tla;
                if (diag) {
                    gB[t] = a; sTailB[t] = tla;
                } else {
                    int b = -1; float tlb = 0.0f;
                    if (t < nb) {
                        int2 e = __ldcg(&g_buck[rowB + t]);
                        b = e.x; tlb = __int_as_float(e.y);
                    }
                    gB[t] = b; sTailB[t] = tlb;
                }
            }
            __syncthreads();

            // stage normalized 64-dim heads (diagonal items stage one tile only)
            for (int i = t; i < TS * H4; i += NT) {
                int r = i >> 4, k4 = i & 15;
                float4 va = make_float4(0.f, 0.f, 0.f, 0.f);
                int g = gA[r];
                if (g >= 0) {
                    va = k4g[g * D4 + k4];
                    float sc = g_invn[g];
                    va.x *= sc; va.y *= sc; va.z *= sc; va.w *= sc;
                }
                sA[r * PH + k4] = va;
                if (!diag) {
                    float4 vb = make_float4(0.f, 0.f, 0.f, 0.f);
                    g = gB[r];
                    if (g >= 0) {
                        vb = k4g[g * D4 + k4];
                        float sc = g_invn[g];
                        vb.x *= sc; vb.y *= sc; vb.z *= sc; vb.w *= sc;
                    }
                    sB[r * PH + k4] = vb;
                }
            }
            __syncthreads();

            const float4* sBp = diag ? sA : sB;
            int ra = t & 31;
            int rq = t >> 5;
            float a0 = 0.f, a1 = 0.f, a2 = 0.f, a3 = 0.f;
            #pragma unroll
            for (int k4 = 0; k4 < H4; k4++) {
                float4 a  = sA[ra * PH + k4];
                float4 b0 = sBp[(rq      ) * PH + k4];
                float4 b1 = sBp[(rq +  8 ) * PH + k4];
                float4 b2 = sBp[(rq + 16 ) * PH + k4];
                float4 b3 = sBp[(rq + 24 ) * PH + k4];
                a0 += a.x * b0.x + a.y * b0.y + a.z * b0.z + a.w * b0.w;
                a1 += a.x * b1.x + a.y * b1.y + a.z * b1.z + a.w * b1.w;
                a2 += a.x * b2.x + a.y * b2.y + a.z * b2.z + a.w * b2.w;
                a3 += a.x * b3.x + a.y * b3.y + a.z * b3.z + a.w * b3.w;
            }
            if (ra < na) {
                int ga = gA[ra];
                float tA = sTailA[ra];
                float accs[4] = {a0, a1, a2, a3};
                #pragma unroll
                for (int j = 0; j < 4; j++) {
                    int rb = rq + 8 * j;
                    if (rb < nb) {
                        int gb = gB[rb];
                        if (gb != ga && accs[j] + tA * sTailB[rb] >= THRESH) {
                            // C-S bound passed: exact full 256-dim dot from L2
                            float invA = g_invn[ga], invB = g_invn[gb];
                            float d = 0.0f;
                            for (int k = 0; k < D4; k++) {
                                float4 x = __ldg(&k4g[ga * D4 + k]);
                                float4 y = __ldg(&k4g[gb * D4 + k]);
                                d += x.x * y.x + x.y * y.y + x.z * y.z + x.w * y.w;
                            }
                            if (d * invA * invB >= THRESH) {
                                int lo2 = min(ga, gb), hi2 = max(ga, gb);
                                atomicMin(&g_claim[hi2], lo2);
                                g_dirty = 1;
                            }
                        }
                    }
                }
            }
            __syncthreads();
        }
    }

    // ---------- exit protocol: all but the LAST block leave immediately ----------
    __threadfence();
    __syncthreads();
    __shared__ int s_last;
    if (t == 0) s_last = (atomicAdd(&g_done, 1u) == GRID - 1) ? 1 : 0;
    __syncthreads();
    if (!s_last) return;

    // ======== LAST BLOCK ONLY from here ========
    const int dirty = __ldcg(&g_dirty);

    if (dirty) {
        // SLOW PATH (rare): exact fixup, single block.
        for (int idx = t; idx < NN; idx += NT) {
            int c = __ldcg(&g_claim[idx]);
            bool keep = (c == idx);
            bool owner_kept = (__ldcg(&g_claim[c]) == c);
            if (owner_kept) atomicAdd(&g_cnt2[c], 1);
            if (!keep) {
                out[NN * DD + idx]          = -1.0f;
                out[NN * DD + NN + idx]     = 0.0f;
                out[NN * DD + 2 * NN + idx] = 0.0f;
                float4 z = make_float4(0.f, 0.f, 0.f, 0.f);
                #pragma unroll 4
                for (int k = 0; k < D4; k++) out4[idx * D4 + k] = z;
                if (owner_kept) {
                    #pragma unroll 4
                    for (int k = 0; k < D4; k++) out4[c * D4 + k] = z;
                }
            }
        }
        __syncthreads();
        for (int j = wp; j < NN; j += 8) {
            int i = 0, n = 0;
            if (lane == 0) {
                i = __ldcg(&g_claim[j]);
                n = (__ldcg(&g_claim[i]) == i) ? __ldcg(&g_cnt2[i]) : 0;
            }
            i = __shfl_sync(0xFFFFFFFFu, i, 0);
            n = __shfl_sync(0xFFFFFFFFu, n, 0);
            if (n <= 1) continue;   // n==1 singleton already correct; n==0 owner dropped
            float4 v0 = k4g[j * D4 + lane];
            float4 v1 = k4g[j * D4 + 32 + lane];
            float w = 1.0f / (float)n;
            atomicAdd(&out[i * DD + lane * 4 + 0],       v0.x * w);
            atomicAdd(&out[i * DD + lane * 4 + 1],       v0.y * w);
            atomicAdd(&out[i * DD + lane * 4 + 2],       v0.z * w);
            atomicAdd(&out[i * DD + lane * 4 + 3],       v0.w * w);
            atomicAdd(&out[i * DD + 128 + lane * 4 + 0], v1.x * w);
            atomicAdd(&out[i * DD + 128 + lane * 4 + 1], v1.y * w);
            atomicAdd(&out[i * DD + 128 + lane * 4 + 2], v1.z * w);
            atomicAdd(&out[i * DD + 128 + lane * 4 + 3], v1.w * w);
        }
        __syncthreads();
    }

    // restore ALL invariants for the next graph replay (g_bar_gen stays monotonic)
    if (t < NC) g_cnt[t] = 0;
    if (t < 8)  g_sub[t] = 0;
    if (t == 8)  g_master = 0;
    if (t == 9)  g_done = 0;
    if (t == 10) g_dirty = 0;
}

// ---------------- launch ----------------
extern "C" void kernel_launch(void* const* d_in, const int* in_sizes, int n_in,
                              void* d_out, int out_size) {
    const float* kin    = (const float*)d_in[0];
    const int*   cat    = (const int*)d_in[1];
    const float* scores = (const float*)d_in[2];
    float*       out    = (float*)d_out;

    (void)in_sizes; (void)n_in; (void)out_size;

    const int smem = 2 * TS * PH * (int)sizeof(float4);  // 17,408 B
    cudaFuncSetAttribute(k_all, cudaFuncAttributeMaxDynamicSharedMemorySize, smem);

    k_all<<<GRID, NT, smem>>>(kin, cat, scores, out);
}